// round 17
// baseline (speedup 1.0000x reference)
#include <cuda_runtime.h>
#include <cuda_fp16.h>
#include <cstdint>

#define B_SZ 4
#define L_SZ 1024
#define DM   1024
#define DI   2048
#define DS   16
#define DTR  64
#define NTOK (B_SZ * L_SZ)   // 4096

// ---------------- scratch ---------------------------------------------------
__device__ float g_xz[NTOK * 2 * DI];        // in_proj output [m][4096]
__device__ float g_dtT[NTOK * DI];           // [b, d, t]
__device__ float g_xcT[NTOK * DI];           // [b, d, t]
__device__ float g_Bm[NTOK * DS];
__device__ float g_Cm[NTOK * DS];
__device__ unsigned char g_maskc[NTOK];

// fp16 operands
__device__ __half g_nh[NTOK * DM];
__device__ __half g_wih[2 * DI * DM];
__device__ __half g_yh[NTOK * DI];
__device__ __half g_woh[DM * DI];
__device__ __half g_xch[NTOK * DI];          // conv output fp16 (xproj A)
__device__ __half g_dtr_h[NTOK * DTR];       // dt_r fp16 (dtproj A)
__device__ __half g_xpwh[128 * DI];          // x_proj_w padded to 128 rows
__device__ __half g_dtwh[DI * DTR];          // dt_proj_w fp16

// ======================= base-ISA helpers ==================================
__device__ __forceinline__ uint32_t smem_u32(const void* p) {
    uint32_t a;
    asm("{ .reg .u64 t; cvta.to.shared.u64 t, %1; cvt.u32.u64 %0, t; }" : "=r"(a) : "l"(p));
    return a;
}
__device__ __forceinline__ void cp_async16(uint32_t dst, const void* src) {
    asm volatile("cp.async.cg.shared.global [%0], [%1], 16;" :: "r"(dst), "l"(src) : "memory");
}
#define CP_COMMIT() asm volatile("cp.async.commit_group;" ::: "memory")
#define CP_WAIT2()  asm volatile("cp.async.wait_group 2;" ::: "memory")

__device__ __forceinline__ void ldsm4(uint32_t* r, uint32_t a) {
    asm volatile("ldmatrix.sync.aligned.m8n8.x4.shared.b16 {%0,%1,%2,%3}, [%4];"
        : "=r"(r[0]), "=r"(r[1]), "=r"(r[2]), "=r"(r[3]) : "r"(a));
}
__device__ __forceinline__ void mma16816h(float* c, const uint32_t* a, const uint32_t* b) {
    asm volatile("mma.sync.aligned.m16n8k16.row.col.f32.f16.f16.f32 "
        "{%0,%1,%2,%3}, {%4,%5,%6,%7}, {%8,%9}, {%0,%1,%2,%3};"
        : "+f"(c[0]), "+f"(c[1]), "+f"(c[2]), "+f"(c[3])
        : "r"(a[0]), "r"(a[1]), "r"(a[2]), "r"(a[3]), "r"(b[0]), "r"(b[1]));
}

// ---------------- mask canonicalization (own launch: slot bookkeeping) ------
__global__ void mask_prep_kernel(const void* maskraw) {
    __shared__ int isint;
    if (threadIdx.x == 0) {
        const unsigned char* p = (const unsigned char*)maskraw;
        int nz = 0;
        for (int i = 0; i < 32; i++)
            nz += (p[i * 4 + 1] != 0) + (p[i * 4 + 2] != 0) + (p[i * 4 + 3] != 0);
        isint = (nz == 0);
    }
    __syncthreads();
    int ii = isint;
    for (int i = threadIdx.x; i < NTOK; i += 256) {
        unsigned char v;
        if (ii) v = (((const int*)maskraw)[i] != 0);
        else    v = (((const unsigned char*)maskraw)[i] != 0);
        g_maskc[i] = v;
    }
}

// ---------------- fused fp32 -> fp16 weight converts (one launch) -----------
#define N_WIN4  ((2 * DI * DM) / 4)      // 1048576
#define N_WOUT4 ((DM * DI) / 4)          // 524288
#define N_XP4   ((128 * DI) / 4)         // 65536
#define N_DT4   ((DI * DTR) / 4)         // 32768
#define N_CVT4  (N_WIN4 + N_WOUT4 + N_XP4 + N_DT4)

__global__ __launch_bounds__(256) void cvt_all_kernel(const float* __restrict__ win,
                                                      const float* __restrict__ wout,
                                                      const float* __restrict__ xpw,
                                                      const float* __restrict__ dtw) {
    int i = blockIdx.x * 256 + threadIdx.x;
    if (i < N_WIN4) {
        float4 v = ((const float4*)win)[i];
        __half2* hp = (__half2*)(g_wih + i * 4);
        hp[0] = __floats2half2_rn(v.x, v.y);
        hp[1] = __floats2half2_rn(v.z, v.w);
    } else if (i < N_WIN4 + N_WOUT4) {
        int j = i - N_WIN4;
        float4 v = ((const float4*)wout)[j];
        __half2* hp = (__half2*)(g_woh + j * 4);
        hp[0] = __floats2half2_rn(v.x, v.y);
        hp[1] = __floats2half2_rn(v.z, v.w);
    } else if (i < N_WIN4 + N_WOUT4 + N_XP4) {
        int j = i - N_WIN4 - N_WOUT4;
        int idx = j * 4;
        int row = idx >> 11;
        __half2 h0, h1;
        if (row < 96) {
            float4 v = ((const float4*)xpw)[j];
            h0 = __floats2half2_rn(v.x, v.y);
            h1 = __floats2half2_rn(v.z, v.w);
        } else {
            h0 = __floats2half2_rn(0.f, 0.f);
            h1 = h0;
        }
        ((__half2*)&g_xpwh[idx])[0] = h0;
        ((__half2*)&g_xpwh[idx])[1] = h1;
    } else if (i < N_CVT4) {
        int j = i - N_WIN4 - N_WOUT4 - N_XP4;
        float4 v = ((const float4*)dtw)[j];
        ((__half2*)&g_dtwh[j * 4])[0] = __floats2half2_rn(v.x, v.y);
        ((__half2*)&g_dtwh[j * 4])[1] = __floats2half2_rn(v.z, v.w);
    }
}

// ---------------- rmsnorm ---------------------------------------------------
__global__ __launch_bounds__(256) void rmsnorm_kernel(const float* __restrict__ x,
                                                      const float* __restrict__ w) {
    int m = blockIdx.x;
    const float* xr = x + (size_t)m * DM;
    float s = 0.f;
    for (int i = threadIdx.x; i < DM; i += 256) { float v = xr[i]; s += v * v; }
    __shared__ float red[8];
    for (int o = 16; o; o >>= 1) s += __shfl_xor_sync(0xffffffffu, s, o);
    if ((threadIdx.x & 31) == 0) red[threadIdx.x >> 5] = s;
    __syncthreads();
    if (threadIdx.x < 8) {
        float v = red[threadIdx.x];
        for (int o = 4; o; o >>= 1) v += __shfl_xor_sync(0xffu, v, o);
        if (threadIdx.x == 0) red[0] = v;
    }
    __syncthreads();
    float scale = rsqrtf(red[0] * (1.0f / DM) + 1e-6f);
    for (int i = threadIdx.x; i < DM; i += 256)
        g_nh[(size_t)m * DM + i] = __float2half_rn(xr[i] * scale * w[i]);
}

// =================== HMMA fp16 GEMM core (BK=64, 3-stage) ===================
// EPI 0: C store. EPI 1: residual+mask. EPI 2: xproj scatter (dtr/B/C).
// EPI 3: dt bias+softplus+transpose -> g_dtT.
#define G_ROWB   144                     // 64 halves (128B) + 16B pad
#define G_OPB    (128 * G_ROWB)          // 18432
#define G_STAGEB (2 * G_OPB)             // 36864
#define G_SMEM   (3 * G_STAGEB)          // 110592

template <int EPI>
__device__ __forceinline__ void gemm_core(const __half* __restrict__ A,
                                          const __half* __restrict__ W,
                                          float* __restrict__ C, int N, int K,
                                          const float* __restrict__ xres,
                                          const float* __restrict__ bias) {
    extern __shared__ char gsm[];
    uint32_t sbase = smem_u32(gsm);
    const int tid = threadIdx.x;
    const int wid = tid >> 5, lane = tid & 31;
    const int wm = wid & 1, wn = wid >> 1;
    const int bx = blockIdx.x, by = blockIdx.y;

    const __half* srcs[2] = { A + (size_t)by * 128 * K, W + (size_t)bx * 128 * K };

    float acc[4][4][4];
#pragma unroll
    for (int i = 0; i < 4; i++)
#pragma unroll
        for (int j = 0; j < 4; j++)
#pragma unroll
            for (int q = 0; q < 4; q++) acc[i][j][q] = 0.f;

    int lrow[8], lkg[8], lop[8];
#pragma unroll
    for (int p = 0; p < 8; p++) {
        int i = p * 256 + tid;      // 0..2047 (2 ops x 1024 float4)
        lop[p] = i >> 10;
        int w = i & 1023;
        lrow[p] = w >> 3;
        lkg[p] = w & 7;
    }

    auto load_stage = [&](int s, int k0) {
        if (k0 < K) {
            uint32_t sb = sbase + s * G_STAGEB;
#pragma unroll
            for (int p = 0; p < 8; p++) {
                const __half* src = srcs[lop[p]] + (size_t)lrow[p] * K + k0 + lkg[p] * 8;
                cp_async16(sb + lop[p] * G_OPB + lrow[p] * G_ROWB + lkg[p] * 16, src);
            }
        }
        CP_COMMIT();
    };

    const int NC = K >> 6;
    load_stage(0, 0);
    load_stage(1, 64);
    load_stage(2, 128);

    const int a_row = wm * 64 + (lane & 15);
    const int a_cb  = (lane >> 4) * 16;
    const int w_row = wn * 32 + (lane & 7) + ((lane >> 4) & 1) * 8;
    const int w_cb  = ((lane >> 3) & 1) * 16;

    int sidx = 0;
    for (int ch = 0; ch < NC; ++ch) {
        CP_WAIT2();
        __syncthreads();
        uint32_t st = sbase + sidx * G_STAGEB;
        uint32_t ah = st, wh = st + G_OPB;
#pragma unroll
        for (int kk = 0; kk < 4; ++kk) {
            int kb = kk * 32;
            uint32_t fA[4][4], fW[4][2];
#pragma unroll
            for (int mt = 0; mt < 4; mt++) {
                uint32_t off = (uint32_t)(a_row + mt * 16) * G_ROWB + a_cb + kb;
                ldsm4(fA[mt], ah + off);
            }
#pragma unroll
            for (int p = 0; p < 2; p++) {
                uint32_t off = (uint32_t)(w_row + p * 16) * G_ROWB + w_cb + kb;
                uint32_t r[4];
                ldsm4(r, wh + off);
                fW[p * 2][0] = r[0]; fW[p * 2][1] = r[1];
                fW[p * 2 + 1][0] = r[2]; fW[p * 2 + 1][1] = r[3];
            }
#pragma unroll
            for (int mt = 0; mt < 4; mt++)
#pragma unroll
                for (int nt = 0; nt < 4; nt++)
                    mma16816h(acc[mt][nt], fA[mt], fW[nt]);
        }
        __syncthreads();
        load_stage(sidx, (ch + 3) * 64);     // guarded; empty commit past K
        sidx = (sidx == 2) ? 0 : sidx + 1;
    }

    if (EPI == 0 || EPI == 1) {
        const int r0 = by * 128 + wm * 64 + (lane >> 2);
        const int c0 = bx * 128 + wn * 32 + (lane & 3) * 2;
#pragma unroll
        for (int mt = 0; mt < 4; mt++) {
            int rowA = r0 + mt * 16, rowB = rowA + 8;
            int mA = (EPI == 1) ? (int)g_maskc[rowA] : 1;
            int mB = (EPI == 1) ? (int)g_maskc[rowB] : 1;
#pragma unroll
            for (int nt = 0; nt < 4; nt++) {
                int col = c0 + nt * 8;
                float2 vA = make_float2(acc[mt][nt][0], acc[mt][nt][1]);
                float2 vB = make_float2(acc[mt][nt][2], acc[mt][nt][3]);
                if (EPI == 1) {
                    if (mA) {
                        float2 r = *(const float2*)(xres + (size_t)rowA * N + col);
                        vA.x += r.x; vA.y += r.y;
                    } else vA = make_float2(0.f, 0.f);
                    if (mB) {
                        float2 r = *(const float2*)(xres + (size_t)rowB * N + col);
                        vB.x += r.x; vB.y += r.y;
                    } else vB = make_float2(0.f, 0.f);
                }
                *(float2*)(C + (size_t)rowA * N + col) = vA;
                *(float2*)(C + (size_t)rowB * N + col) = vB;
            }
        }
    } else if (EPI == 2) {
        const int r0 = by * 128 + wm * 64 + (lane >> 2);
        const int c0 = wn * 32 + (lane & 3) * 2;
#pragma unroll
        for (int mt = 0; mt < 4; mt++) {
            int rowA = r0 + mt * 16, rowB = rowA + 8;
#pragma unroll
            for (int nt = 0; nt < 4; nt++) {
                int col = c0 + nt * 8;
                if (col < 64) {
                    *(__half2*)&g_dtr_h[rowA * DTR + col] =
                        __floats2half2_rn(acc[mt][nt][0], acc[mt][nt][1]);
                    *(__half2*)&g_dtr_h[rowB * DTR + col] =
                        __floats2half2_rn(acc[mt][nt][2], acc[mt][nt][3]);
                } else if (col < 80) {
                    *(float2*)&g_Bm[rowA * DS + col - 64] =
                        make_float2(acc[mt][nt][0], acc[mt][nt][1]);
                    *(float2*)&g_Bm[rowB * DS + col - 64] =
                        make_float2(acc[mt][nt][2], acc[mt][nt][3]);
                } else if (col < 96) {
                    *(float2*)&g_Cm[rowA * DS + col - 80] =
                        make_float2(acc[mt][nt][0], acc[mt][nt][1]);
                    *(float2*)&g_Cm[rowB * DS + col - 80] =
                        make_float2(acc[mt][nt][2], acc[mt][nt][3]);
                }
            }
        }
    } else {
        const int b  = (by * 128) >> 10;
        const int t0 = (by * 128) & (L_SZ - 1);
        float* stage = (float*)gsm;          // [64][132] per pass
#pragma unroll
        for (int pass = 0; pass < 2; ++pass) {
            __syncthreads();
            if ((wn >> 1) == pass) {
                int clbase = (wn & 1) * 32 + (lane & 3) * 2;
#pragma unroll
                for (int mt = 0; mt < 4; mt++) {
                    int rA = wm * 64 + mt * 16 + (lane >> 2);
#pragma unroll
                    for (int nt = 0; nt < 4; nt++) {
                        int cl = clbase + nt * 8;
                        int dcol = bx * 128 + pass * 64 + cl;
                        float b0 = bias[dcol], b1 = bias[dcol + 1];
                        float v;
                        v = acc[mt][nt][0] + b0;
                        stage[cl * 132 + rA] = (v > 20.f) ? v : log1pf(__expf(v));
                        v = acc[mt][nt][1] + b1;
                        stage[(cl + 1) * 132 + rA] = (v > 20.f) ? v : log1pf(__expf(v));
                        v = acc[mt][nt][2] + b0;
                        stage[cl * 132 + rA + 8] = (v > 20.f) ? v : log1pf(__expf(v));
                        v = acc[mt][nt][3] + b1;
                        stage[(cl + 1) * 132 + rA + 8] = (v > 20.f) ? v : log1pf(__expf(v));
                    }
                }
            }
            __syncthreads();
            int dl = tid >> 2, tq = tid & 3;
            float* dst = &g_dtT[((size_t)b * DI + bx * 128 + pass * 64 + dl) * L_SZ
                                + t0 + tq * 32];
            const float* srcp = stage + dl * 132 + tq * 32;
#pragma unroll
            for (int i = 0; i < 8; i++)
                ((float4*)dst)[i] = ((const float4*)srcp)[i];
        }
    }
}

__global__ __launch_bounds__(256) void gemm_inproj_kernel() {
    gemm_core<0>(g_nh, g_wih, g_xz, 2 * DI, DM, nullptr, nullptr);
}
__global__ __launch_bounds__(256) void gemm_outproj_kernel(const float* __restrict__ x,
                                                           float* __restrict__ out) {
    gemm_core<1>(g_yh, g_woh, out, DM, DI, x, nullptr);
}
__global__ __launch_bounds__(256) void gemm_xproj_kernel() {
    gemm_core<2>(g_xch, g_xpwh, nullptr, 128, DI, nullptr, nullptr);
}
__global__ __launch_bounds__(256) void gemm_dt_kernel(const float* __restrict__ dtb) {
    gemm_core<3>(g_dtr_h, g_dtwh, nullptr, 128, DTR, nullptr, dtb);
}

// ---------------- conv + silu (writes xch fp16, xcT fp32) -------------------
__global__ __launch_bounds__(256) void conv_silu_kernel(const float* __restrict__ convw,
                                                        const float* __restrict__ convb) {
    int c = blockIdx.x * 256 + threadIdx.x;
    int m0 = blockIdx.y * 8;
    int b = m0 >> 10, t0 = m0 & (L_SZ - 1);
    unsigned char mk[11];
#pragma unroll
    for (int r = 0; r < 11; r++) {
        int mrow = m0 - 3 + r;
        mk[r] = (mrow >= 0) ? g_maskc[mrow] : (unsigned char)0;
    }
    float w0 = convw[c * 4 + 0], w1 = convw[c * 4 + 1];
    float w2 = convw[c * 4 + 2], w3 = convw[c * 4 + 3];
    float cb = convb[c];
    float xr[11];
#pragma unroll
    for (int r = 0; r < 11; r++) {
        int mrow = m0 - 3 + r;
        xr[r] = (mrow >= 0) ? g_xz[(size_t)mrow * (2 * DI) + c] : 0.f;
    }
    float xcv[8];
#pragma unroll
    for (int tt = 0; tt < 8; tt++) {
        int tloc = t0 + tt;
        float acc = cb;
        if (mk[tt + 3]) {
            acc += w3 * xr[tt + 3];
            if (tloc >= 1 && mk[tt + 2]) {
                acc += w2 * xr[tt + 2];
                if (tloc >= 2 && mk[tt + 1]) {
                    acc += w1 * xr[tt + 1];
                    if (tloc >= 3 && mk[tt]) acc += w0 * xr[tt];
                }
            }
        }
        float s = acc / (1.0f + __expf(-acc));
        xcv[tt] = s;
        g_xch[(size_t)(m0 + tt) * DI + c] = __float2half_rn(s);
    }
    float4* p = (float4*)&g_xcT[((size_t)b * DI + c) * L_SZ + t0];
    p[0] = make_float4(xcv[0], xcv[1], xcv[2], xcv[3]);
    p[1] = make_float4(xcv[4], xcv[5], xcv[6], xcv[7]);
}

// ====== scan (16-lane layout, fused gating) + smem-staged B/C ===============
__global__ __launch_bounds__(256) void scan_kernel(const float* __restrict__ A_log,
                                                   const float* __restrict__ Dp) {
    __shared__ float sB[128 * DS];   // 8 KB
    __shared__ float sC[128 * DS];   // 8 KB
    int gid = (blockIdx.x * 256 + threadIdx.x) >> 4;
    int s = threadIdx.x & 15;
    int b = gid >> 11;
    int d = gid & (DI - 1);
    float a  = -__expf(A_log[d * DS + s]);
    float Dv = Dp[d];
    const float* dtp = g_dtT + (size_t)(b * DI + d) * L_SZ;
    const float* xcp = g_xcT + (size_t)(b * DI + d) * L_SZ;
    const float* Bfull = g_Bm + (size_t)b * L_SZ * DS;
    const float* Cfull = g_Cm + (size_t)b * L_SZ * DS;
    const unsigned char* mp = g_maskc + b * L_SZ;

    float h = 0.f, ybuf = 0.f, xbuf = 0.f;
    for (int tc = 0; tc < L_SZ; tc += 128) {
        __syncthreads();
        {
            const float4* sb = (const float4*)(Bfull + tc * DS);
            const float4* sc = (const float4*)(Cfull + tc * DS);
            ((float4*)sB)[threadIdx.x]       = sb[threadIdx.x];
            ((float4*)sB)[threadIdx.x + 256] = sb[threadIdx.x + 256];
            ((float4*)sC)[threadIdx.x]       = sc[threadIdx.x];
            ((float4*)sC)[threadIdx.x + 256] = sc[threadIdx.x + 256];
        }
        __syncthreads();
#pragma unroll 4
        for (int t4 = tc; t4 < tc + 128; t4 += 4) {
            float4 dt4 = *(const float4*)(dtp + t4);
            float4 xc4 = *(const float4*)(xcp + t4);
            unsigned int mu = *(const unsigned int*)(mp + t4);
            float dts[4] = {dt4.x, dt4.y, dt4.z, dt4.w};
            float xcs[4] = {xc4.x, xc4.y, xc4.z, xc4.w};
#pragma unroll
            for (int q = 0; q < 4; q++) {
                int t = t4 + q;
                float Bv = sB[((t & 127) << 4) + s];
                float Cv = sC[((t & 127) << 4) + s];
                float dA = __expf(dts[q] * a);
                float hn = fmaf(dA, h, dts[q] * Bv * xcs[q]);
                h = ((mu >> (q * 8)) & 255u) ? hn : 0.f;
                float p = h * Cv;
                p += __shfl_xor_sync(0xffffffffu, p, 8);
                p += __shfl_xor_sync(0xffffffffu, p, 4);
                p += __shfl_xor_sync(0xffffffffu, p, 2);
                p += __shfl_xor_sync(0xffffffffu, p, 1);
                if ((t & 15) == s) { ybuf = p; xbuf = xcs[q]; }
                if ((t & 15) == 15) {
                    size_t m = (size_t)b * L_SZ + (t & ~15) + s;
                    float zv = g_xz[m * (2 * DI) + DI + d];
                    float sz = zv / (1.0f + __expf(-zv));
                    float yy = fmaf(Dv, xbuf, ybuf);
                    g_yh[m * DI + d] = __float2half_rn(yy * sz);
                }
            }
        }
    }
}

// ---------------- launch ----------------------------------------------------
extern "C" void kernel_launch(void* const* d_in, const int* in_sizes, int n_in,
                              void* d_out, int out_size) {
    const float* x        = (const float*)d_in[0];
    const void*  maskraw  = d_in[1];
    const float* rms_w    = (const float*)d_in[2];
    const float* in_proj  = (const float*)d_in[3];
    const float* conv_w   = (const float*)d_in[4];
    const float* conv_b   = (const float*)d_in[5];
    const float* x_proj   = (const float*)d_in[6];
    const float* dt_proj  = (const float*)d_in[7];
    const float* dt_b     = (const float*)d_in[8];
    const float* A_log    = (const float*)d_in[9];
    const float* Dvec     = (const float*)d_in[10];
    const float* out_proj = (const float*)d_in[11];
    float* out = (float*)d_out;

    cudaFuncSetAttribute(gemm_inproj_kernel,  cudaFuncAttributeMaxDynamicSharedMemorySize, G_SMEM);
    cudaFuncSetAttribute(gemm_outproj_kernel, cudaFuncAttributeMaxDynamicSharedMemorySize, G_SMEM);
    cudaFuncSetAttribute(gemm_xproj_kernel,   cudaFuncAttributeMaxDynamicSharedMemorySize, G_SMEM);
    cudaFuncSetAttribute(gemm_dt_kernel,      cudaFuncAttributeMaxDynamicSharedMemorySize, G_SMEM);

    // 1 mask, 2 rmsnorm, 3 cvt_all, 4 gemm_in (profiled), 5 conv, 6 xproj,
    // 7 dt, 8 scan, 9 gemm_out
    mask_prep_kernel<<<1, 256>>>(maskraw);
    rmsnorm_kernel<<<NTOK, 256>>>(x, rms_w);
    cvt_all_kernel<<<(N_CVT4 + 255) / 256, 256>>>(in_proj, out_proj, x_proj, dt_proj);

    dim3 g1((2 * DI) / 128, NTOK / 128);
    gemm_inproj_kernel<<<g1, 256, G_SMEM>>>();

    dim3 gc(DI / 256, NTOK / 8);
    conv_silu_kernel<<<gc, 256>>>(conv_w, conv_b);

    dim3 gx(1, NTOK / 128);
    gemm_xproj_kernel<<<gx, 256, G_SMEM>>>();

    dim3 gd(DI / 128, NTOK / 128);
    gemm_dt_kernel<<<gd, 256, G_SMEM>>>(dt_b);

    scan_kernel<<<(B_SZ * DI * DS) / 256, 256>>>(A_log, Dvec);

    dim3 g2(DM / 128, NTOK / 128);
    gemm_outproj_kernel<<<g2, 256, G_SMEM>>>(x, out);
}